// round 15
// baseline (speedup 1.0000x reference)
#include <cuda_runtime.h>
#include <cuda_fp16.h>
#include <cstdint>

// ---------------------------------------------------------------------------
// Problem shape
// ---------------------------------------------------------------------------
constexpr int M_ENS = 8, B_DIM = 4096, I_DIM = 2048, O_DIM = 2048;

// GEMM tiling: CTA = 128x128, K-tile 64, 4 warps (2x2), 2 CTAs/SM.
constexpr int CT_M = 128, CT_N = 128, CT_K = 64;
constexpr int NKT = I_DIM / CT_K;    // 32
constexpr int NBT = B_DIM / CT_M;    // 32
constexpr int NOT16 = O_DIM / CT_N;  // 16
constexpr int IMG_BYTES = CT_M * CT_K * 2;      // 16384
constexpr int STAGE_BYTES = 2 * IMG_BYTES;      // 32768
constexpr int STAGES = 3;
constexpr int SMEM_CTRL = 128;
constexpr int SMEM_BYTES = SMEM_CTRL + STAGES * STAGE_BYTES;  // 98432

// prep item enumeration: x images, w images, bias chunks
constexpr int PX_ITEMS = M_ENS * NBT * NKT;      // 8192
constexpr int PW_ITEMS = M_ENS * NOT16 * NKT;    // 4096
constexpr int PB_ITEMS = (M_ENS * O_DIM) / 128;  // 128
constexpr int NPREP_ITEMS = PX_ITEMS + PW_ITEMS + PB_ITEMS;  // 12416

// ---------------------------------------------------------------------------
// Scratch (device globals; no cudaMalloc allowed).
// Images: pre-swizzled smem images (layout per round-7 comment).
// ---------------------------------------------------------------------------
__device__ __align__(128) __half g_Xs[(size_t)M_ENS * B_DIM * I_DIM];
__device__ __align__(128) __half g_Ws[(size_t)M_ENS * O_DIM * I_DIM];
__device__ float g_bias[M_ENS * O_DIM];

// ---------------------------------------------------------------------------
// Helpers
// ---------------------------------------------------------------------------
__device__ __forceinline__ float softplus_f(float r) {
    return (r > 15.0f) ? r : log1pf(__expf(r));
}
__device__ __forceinline__ uint32_t smem_u32_of(const void* p) {
    uint32_t a;
    asm("{ .reg .u64 t; cvta.to.shared.u64 t, %1; cvt.u32.u64 %0, t; }"
        : "=r"(a) : "l"(p));
    return a;
}
__device__ __forceinline__ uint32_t rev3(uint32_t x) {
    return ((x & 1u) << 2) | (x & 2u) | ((x >> 2) & 1u);
}
__device__ __forceinline__ void mbar_init(uint32_t mbar, uint32_t cnt) {
    asm volatile("mbarrier.init.shared.b64 [%0], %1;" :: "r"(mbar), "r"(cnt) : "memory");
}
__device__ __forceinline__ void mbar_expect_tx(uint32_t mbar, uint32_t bytes) {
    asm volatile("mbarrier.arrive.expect_tx.shared.b64 _, [%0], %1;"
                 :: "r"(mbar), "r"(bytes) : "memory");
}
__device__ __forceinline__ void mbar_arrive(uint32_t mbar) {
    asm volatile("mbarrier.arrive.shared.b64 _, [%0];" :: "r"(mbar) : "memory");
}
__device__ __forceinline__ void mbar_wait(uint32_t mbar, uint32_t parity) {
    asm volatile(
        "{\n\t.reg .pred P;\n\t"
        "W_%=:\n\t"
        "mbarrier.try_wait.parity.acquire.cta.shared::cta.b64 P, [%0], %1, 0x989680;\n\t"
        "@P bra.uni D_%=;\n\t"
        "bra.uni W_%=;\n\t"
        "D_%=:\n\t}"
        :: "r"(mbar), "r"(parity) : "memory");
}
__device__ __forceinline__ void bulk_g2s(uint32_t dst, const void* src,
                                         uint32_t bytes, uint32_t mbar) {
    asm volatile(
        "cp.async.bulk.shared::cluster.global.mbarrier::complete_tx::bytes "
        "[%0], [%1], %2, [%3];"
        :: "r"(dst), "l"(src), "r"(bytes), "r"(mbar) : "memory");
}
__device__ __forceinline__ void mma_f16(float* c, uint32_t a0, uint32_t a1,
                                        uint32_t a2, uint32_t a3,
                                        uint32_t b0, uint32_t b1) {
    asm volatile(
        "mma.sync.aligned.m16n8k16.row.col.f32.f16.f16.f32 "
        "{%0,%1,%2,%3}, {%4,%5,%6,%7}, {%8,%9}, {%0,%1,%2,%3};"
        : "+f"(c[0]), "+f"(c[1]), "+f"(c[2]), "+f"(c[3])
        : "r"(a0), "r"(a1), "r"(a2), "r"(a3), "r"(b0), "r"(b1));
}

// ---------------------------------------------------------------------------
// Prep kernel: one image (or bias chunk) per 128-thread block, 17.4KB
// scratch (half-tiles). Unchanged from round 14 (147us, ~done).
// ---------------------------------------------------------------------------
__global__ __launch_bounds__(128)
void prep_all_kernel(const float* __restrict__ x,
                     const float* __restrict__ mu,
                     const float* __restrict__ rho,
                     const float* __restrict__ eps,
                     const float* __restrict__ bmu,
                     const float* __restrict__ brho,
                     const float* __restrict__ beps) {
    __shared__ __align__(16) float sraw[64 * 68];   // 17408 B
    const int gb = blockIdx.x;
    const int t = threadIdx.x;

    if (gb < PX_ITEMS) {
        // ---- x image (two 64-row halves) ----
        const int kt = gb & 31, bt = (gb >> 5) & 31, m = gb >> 10;
        float (*tl)[68] = reinterpret_cast<float(*)[68]>(sraw);
        char* img = (char*)g_Xs + ((size_t)((m * NBT + bt) * NKT + kt)) * IMG_BYTES;
#pragma unroll
        for (int half = 0; half < 2; half++) {
            const float* src =
                x + ((size_t)(m * B_DIM + bt * 128 + half * 64)) * I_DIM + kt * 64;
#pragma unroll
            for (int i = 0; i < 8; i++) {           // 64 rows x 16 float4
                int c = t + i * 128;
                int r = c >> 4, q = c & 15;
                float4 v = *reinterpret_cast<const float4*>(src + (size_t)r * I_DIM + q * 4);
                *reinterpret_cast<float4*>(&tl[r][q * 4]) = v;
            }
            __syncthreads();
#pragma unroll
            for (int i = 0; i < 4; i++) {           // 512 granule slots
                int c = t + i * 128;
                int r = c >> 3, j = c & 7;
                int kb = j >> 2, tt2 = j & 3;
                __half h[8];
#pragma unroll
                for (int u = 0; u < 8; u++) {
                    int k = kb * 32 + 2 * tt2 + (u & 1) + ((u >> 1) & 1) * 8 +
                            ((u >> 2) & 1) * 16;
                    h[u] = __float2half_rn(tl[r][k]);
                }
                uint32_t off = (uint32_t)(half * 64 + r) * 128 +
                               ((((uint32_t)j) << 4) ^ (rev3((uint32_t)r & 7) << 4));
                *reinterpret_cast<uint4*>(img + off) = *reinterpret_cast<uint4*>(h);
            }
            __syncthreads();
        }
    } else if (gb < PX_ITEMS + PW_ITEMS) {
        // ---- w image (two 32-k halves) ----
        const int g = gb - PX_ITEMS;
        const int kt = g & 31, ot = (g >> 5) & 15, m = g >> 9;
        float (*tl)[132] = reinterpret_cast<float(*)[132]>(sraw);   // 32x132
        char* img = (char*)g_Ws + ((size_t)((m * NOT16 + ot) * NKT + kt)) * IMG_BYTES;
#pragma unroll
        for (int kb = 0; kb < 2; kb++) {
            const size_t base = (size_t)m * I_DIM * O_DIM +
                                (size_t)(kt * 64 + kb * 32) * O_DIM + ot * 128;
#pragma unroll
            for (int i = 0; i < 8; i++) {           // 32 rows x 32 float4
                int c = t + i * 128;
                int r = c >> 5, qq = c & 31;
                size_t idx = base + (size_t)r * O_DIM + qq * 4;
                float4 vm = *reinterpret_cast<const float4*>(mu + idx);
                float4 vr = *reinterpret_cast<const float4*>(rho + idx);
                float4 ve = *reinterpret_cast<const float4*>(eps + idx);
                float4 w;
                w.x = fmaf(softplus_f(vr.x), ve.x, vm.x);
                w.y = fmaf(softplus_f(vr.y), ve.y, vm.y);
                w.z = fmaf(softplus_f(vr.z), ve.z, vm.z);
                w.w = fmaf(softplus_f(vr.w), ve.w, vm.w);
                *reinterpret_cast<float4*>(&tl[r][qq * 4]) = w;
            }
            __syncthreads();
#pragma unroll
            for (int i = 0; i < 4; i++) {           // 128 o x 4 tt
                int c = t + i * 128;
                int o = c >> 2, tt2 = c & 3;
                int j = kb * 4 + tt2;
                __half h[8];
#pragma unroll
                for (int u = 0; u < 8; u++) {
                    int kl = 2 * tt2 + (u & 1) + ((u >> 1) & 1) * 8 + ((u >> 2) & 1) * 16;
                    h[u] = __float2half_rn(tl[kl][o]);
                }
                uint32_t off = (uint32_t)o * 128 +
                               ((((uint32_t)j) << 4) ^ (rev3((uint32_t)o & 7) << 4));
                *reinterpret_cast<uint4*>(img + off) = *reinterpret_cast<uint4*>(h);
            }
            __syncthreads();
        }
    } else {
        // ---- bias ----
        int i = (gb - PX_ITEMS - PW_ITEMS) * 128 + t;
        g_bias[i] = fmaf(softplus_f(brho[i]), beps[i], bmu[i]);
    }
}

// ---------------------------------------------------------------------------
// GEMM: r11 protocol + mid-tile hoisted full-wait: the wait for stage kt+1
// sits between kb0 and kb1 of tile kt, overlapping its latency with the
// tensor-pipe drain of kb0's 32 freshly issued HMMAs.
// ---------------------------------------------------------------------------
__global__ __launch_bounds__(128, 2)
void gemm_kernel(float* __restrict__ Out) {
    extern __shared__ __align__(128) uint8_t smem_raw[];
    const uint32_t sb = smem_u32_of(smem_raw);
    const int tid = threadIdx.x, lane = tid & 31, wid = tid >> 5;
    const int gid = lane >> 2, tig = lane & 3;
    const int wm = wid >> 1, wn = wid & 1;
    const int ot = blockIdx.x, bt = blockIdx.y, m = blockIdx.z;

    const char* gA = (const char*)g_Xs + (size_t)((m * NBT + bt) * NKT) * IMG_BYTES;
    const char* gB = (const char*)g_Ws + (size_t)((m * NOT16 + ot) * NKT) * IMG_BYTES;

    if (tid == 0) {
#pragma unroll
        for (int s = 0; s < STAGES; s++) {
            mbar_init(sb + 8 * s, 1);
            mbar_init(sb + 24 + 8 * s, 4);
        }
        asm volatile("fence.proxy.async.shared::cta;" ::: "memory");
    }
    __syncthreads();

    if (tid == 0) {
#pragma unroll
        for (int kt = 0; kt < 2; kt++) {
            uint32_t fb = sb + 8 * kt;
            uint32_t st = sb + SMEM_CTRL + kt * STAGE_BYTES;
            mbar_expect_tx(fb, STAGE_BYTES);
            bulk_g2s(st, gA + (size_t)kt * IMG_BYTES, IMG_BYTES, fb);
            bulk_g2s(st + IMG_BYTES, gB + (size_t)kt * IMG_BYTES, IMG_BYTES, fb);
        }
    }

    float acc[4][8][4];
#pragma unroll
    for (int f = 0; f < 4; f++)
#pragma unroll
        for (int n = 0; n < 8; n++)
#pragma unroll
            for (int q = 0; q < 4; q++) acc[f][n][q] = 0.0f;

    const uint32_t arev = rev3(gid) << 4;
    uint32_t aRow[4], bRow[8];
#pragma unroll
    for (int f = 0; f < 4; f++) aRow[f] = (uint32_t)(wm * 64 + f * 16 + gid) * 128;
#pragma unroll
    for (int n = 0; n < 8; n++) bRow[n] = (uint32_t)(wn * 64 + n * 8 + gid) * 128;

    // one-time wait for tile 0 (later tiles are waited mid-previous-tile)
    mbar_wait(sb + 8 * 0, 0);

    constexpr int NROUND = (NKT + 2) / 3;  // 11
    for (int rr = 0; rr < NROUND; rr++) {
        const int phf = rr & 1;
#pragma unroll
        for (int ss = 0; ss < 3; ss++) {
            const int kt = rr * 3 + ss;
            if (kt >= NKT) break;

            // producer: refill s2=(ss+2)%3 with tile kt+2
            if (tid == 0 && kt + 2 < NKT) {
                const int s2 = (ss + 2 >= 3) ? ss - 1 : ss + 2;  // compile-time
                if (kt >= 1) {
                    const int phe = (ss == 0) ? ((rr - 1) & 1) : (rr & 1);
                    mbar_wait(sb + 24 + 8 * s2, phe);
                }
                uint32_t fb = sb + 8 * s2;
                uint32_t st = sb + SMEM_CTRL + s2 * STAGE_BYTES;
                mbar_expect_tx(fb, STAGE_BYTES);
                bulk_g2s(st, gA + (size_t)(kt + 2) * IMG_BYTES, IMG_BYTES, fb);
                bulk_g2s(st + IMG_BYTES, gB + (size_t)(kt + 2) * IMG_BYTES, IMG_BYTES, fb);
            }

            const uint8_t* As = smem_raw + (SMEM_CTRL + ss * STAGE_BYTES);
            const uint8_t* Bs = As + IMG_BYTES;

#pragma unroll
            for (int kb = 0; kb < 2; kb++) {
                const uint32_t gran = (((uint32_t)(kb * 4 + tig)) << 4) ^ arev;
                uint4 aLo[4], aHi[4], bV[8];
#pragma unroll
                for (int f = 0; f < 4; f++) {
                    aLo[f] = *reinterpret_cast<const uint4*>(As + aRow[f] + gran);
                    aHi[f] = *reinterpret_cast<const uint4*>(As + aRow[f] + 8 * 128 + gran);
                }
#pragma unroll
                for (int n = 0; n < 8; n++)
                    bV[n] = *reinterpret_cast<const uint4*>(Bs + bRow[n] + gran);
#pragma unroll
                for (int kg = 0; kg < 2; kg++) {
#pragma unroll
                    for (int f = 0; f < 4; f++) {
                        uint32_t a0 = kg ? aLo[f].z : aLo[f].x;
                        uint32_t a2 = kg ? aLo[f].w : aLo[f].y;
                        uint32_t a1 = kg ? aHi[f].z : aHi[f].x;
                        uint32_t a3 = kg ? aHi[f].w : aHi[f].y;
#pragma unroll
                        for (int n = 0; n < 8; n++) {
                            uint32_t b0 = kg ? bV[n].z : bV[n].x;
                            uint32_t b1 = kg ? bV[n].w : bV[n].y;
                            mma_f16(acc[f][n], a0, a1, a2, a3, b0, b1);
                        }
                    }
                }
                // mid-tile hoisted wait: after kb0's mma are issued (tensor
                // pipe full), wait for the NEXT tile's stage to be ready.
                if (kb == 0 && kt + 1 < NKT) {
                    const int sn = (ss + 1 >= 3) ? 0 : ss + 1;      // compile-time
                    const int phn = (ss == 2) ? ((rr + 1) & 1) : phf;
                    mbar_wait(sb + 8 * sn, phn);
                }
            }
            if (lane == 0) mbar_arrive(sb + 24 + 8 * ss);
        }
    }

    // ---- epilogue: add bias, write out ----
    const float* bias = g_bias + m * O_DIM + ot * CT_N;
    const size_t rowbase = (size_t)m * B_DIM + (size_t)bt * CT_M;
#pragma unroll
    for (int f = 0; f < 4; f++) {
        int r0 = wm * 64 + f * 16 + gid;
#pragma unroll
        for (int n = 0; n < 8; n++) {
            int col = wn * 64 + n * 8 + tig * 2;
            float2 bb = *reinterpret_cast<const float2*>(&bias[col]);
            float2 v0, v1;
            v0.x = acc[f][n][0] + bb.x;
            v0.y = acc[f][n][1] + bb.y;
            v1.x = acc[f][n][2] + bb.x;
            v1.y = acc[f][n][3] + bb.y;
            *reinterpret_cast<float2*>(
                &Out[(rowbase + r0) * O_DIM + (size_t)ot * CT_N + col]) = v0;
            *reinterpret_cast<float2*>(
                &Out[(rowbase + r0 + 8) * O_DIM + (size_t)ot * CT_N + col]) = v1;
        }
    }
}

// ---------------------------------------------------------------------------
// Launch (single stream, graph-safe).
// Inputs: x, weight_mu, weight_rho, bias_mu, bias_rho, eps_w, eps_b
// ---------------------------------------------------------------------------
extern "C" void kernel_launch(void* const* d_in, const int* in_sizes, int n_in,
                              void* d_out, int out_size) {
    const float* x     = (const float*)d_in[0];
    const float* w_mu  = (const float*)d_in[1];
    const float* w_rho = (const float*)d_in[2];
    const float* b_mu  = (const float*)d_in[3];
    const float* b_rho = (const float*)d_in[4];
    const float* eps_w = (const float*)d_in[5];
    const float* eps_b = (const float*)d_in[6];
    float* out = (float*)d_out;

    cudaFuncSetAttribute(gemm_kernel, cudaFuncAttributeMaxDynamicSharedMemorySize,
                         SMEM_BYTES);

    prep_all_kernel<<<NPREP_ITEMS, 128>>>(x, w_mu, w_rho, eps_w,
                                          b_mu, b_rho, eps_b);
    gemm_kernel<<<dim3(NOT16, NBT, M_ENS), 128, SMEM_BYTES>>>(out);
}

// round 16
// speedup vs baseline: 1.0281x; 1.0281x over previous
#include <cuda_runtime.h>
#include <cuda_fp16.h>
#include <cstdint>

// ---------------------------------------------------------------------------
// Problem shape
// ---------------------------------------------------------------------------
constexpr int M_ENS = 8, B_DIM = 4096, I_DIM = 2048, O_DIM = 2048;

// GEMM tiling: CTA = 128x128, K-tile 64, 4 warps (2x2), 2 CTAs/SM.
constexpr int CT_M = 128, CT_N = 128, CT_K = 64;
constexpr int NKT = I_DIM / CT_K;    // 32
constexpr int NBT = B_DIM / CT_M;    // 32
constexpr int NOT16 = O_DIM / CT_N;  // 16
constexpr int IMG_BYTES = CT_M * CT_K * 2;      // 16384
constexpr int STAGE_BYTES = 2 * IMG_BYTES;      // 32768
constexpr int STAGES = 3;
constexpr int SMEM_CTRL = 128;
constexpr int SMEM_BYTES = SMEM_CTRL + STAGES * STAGE_BYTES;  // 98432

// prep enumeration
constexpr int PX_ITEMS = M_ENS * NBT * NKT;      // 8192 x-images
constexpr int PW_ITEMS = M_ENS * NOT16 * NKT;    // 4096 w-images
constexpr int PB_ITEMS = (M_ENS * O_DIM) / 128;  // 128 bias chunks

// ---------------------------------------------------------------------------
// Scratch (device globals; no cudaMalloc allowed).
// Images: pre-swizzled smem images (layout per round-7 comment).
// ---------------------------------------------------------------------------
__device__ __align__(128) __half g_Xs[(size_t)M_ENS * B_DIM * I_DIM];
__device__ __align__(128) __half g_Ws[(size_t)M_ENS * O_DIM * I_DIM];
__device__ float g_bias[M_ENS * O_DIM];

// ---------------------------------------------------------------------------
// Helpers
// ---------------------------------------------------------------------------
__device__ __forceinline__ float softplus_f(float r) {
    // fast softplus: __logf abs err ~4e-7 near 1 -> negligible vs fp16 quant
    return (r > 15.0f) ? r : __logf(1.0f + __expf(r));
}
__device__ __forceinline__ uint32_t smem_u32_of(const void* p) {
    uint32_t a;
    asm("{ .reg .u64 t; cvta.to.shared.u64 t, %1; cvt.u32.u64 %0, t; }"
        : "=r"(a) : "l"(p));
    return a;
}
__device__ __forceinline__ uint32_t rev3(uint32_t x) {
    return ((x & 1u) << 2) | (x & 2u) | ((x >> 2) & 1u);
}
__device__ __forceinline__ void mbar_init(uint32_t mbar, uint32_t cnt) {
    asm volatile("mbarrier.init.shared.b64 [%0], %1;" :: "r"(mbar), "r"(cnt) : "memory");
}
__device__ __forceinline__ void mbar_expect_tx(uint32_t mbar, uint32_t bytes) {
    asm volatile("mbarrier.arrive.expect_tx.shared.b64 _, [%0], %1;"
                 :: "r"(mbar), "r"(bytes) : "memory");
}
__device__ __forceinline__ void mbar_arrive(uint32_t mbar) {
    asm volatile("mbarrier.arrive.shared.b64 _, [%0];" :: "r"(mbar) : "memory");
}
__device__ __forceinline__ void mbar_wait(uint32_t mbar, uint32_t parity) {
    asm volatile(
        "{\n\t.reg .pred P;\n\t"
        "W_%=:\n\t"
        "mbarrier.try_wait.parity.acquire.cta.shared::cta.b64 P, [%0], %1, 0x989680;\n\t"
        "@P bra.uni D_%=;\n\t"
        "bra.uni W_%=;\n\t"
        "D_%=:\n\t}"
        :: "r"(mbar), "r"(parity) : "memory");
}
__device__ __forceinline__ void bulk_g2s(uint32_t dst, const void* src,
                                         uint32_t bytes, uint32_t mbar) {
    asm volatile(
        "cp.async.bulk.shared::cluster.global.mbarrier::complete_tx::bytes "
        "[%0], [%1], %2, [%3];"
        :: "r"(dst), "l"(src), "r"(bytes), "r"(mbar) : "memory");
}
__device__ __forceinline__ void mma_f16(float* c, uint32_t a0, uint32_t a1,
                                        uint32_t a2, uint32_t a3,
                                        uint32_t b0, uint32_t b1) {
    asm volatile(
        "mma.sync.aligned.m16n8k16.row.col.f32.f16.f16.f32 "
        "{%0,%1,%2,%3}, {%4,%5,%6,%7}, {%8,%9}, {%0,%1,%2,%3};"
        : "+f"(c[0]), "+f"(c[1]), "+f"(c[2]), "+f"(c[3])
        : "r"(a0), "r"(a1), "r"(a2), "r"(a3), "r"(b0), "r"(b1));
}

// ---------------------------------------------------------------------------
// Prep X: smem-free. One block per image; one THREAD per row (128 rows).
// Per row: load 2x(8 float4) contiguous, permute in registers, store 8x16B
// into the thread's own 128B image row. No __syncthreads at all.
// ---------------------------------------------------------------------------
__global__ __launch_bounds__(128)
void prep_x_kernel(const float* __restrict__ x) {
    const int gb = blockIdx.x;
    const int kt = gb & 31, bt = (gb >> 5) & 31, m = gb >> 10;
    const int r = threadIdx.x;

    const float* src = x + ((size_t)(m * B_DIM + bt * 128 + r)) * I_DIM + kt * 64;
    char* img = (char*)g_Xs + ((size_t)((m * NBT + bt) * NKT + kt)) * IMG_BYTES +
                (uint32_t)r * 128;
    const uint32_t rx = rev3((uint32_t)r & 7) << 4;

#pragma unroll
    for (int kb = 0; kb < 2; kb++) {
        float in[32];
#pragma unroll
        for (int i = 0; i < 8; i++)
            *reinterpret_cast<float4*>(&in[i * 4]) =
                *reinterpret_cast<const float4*>(src + kb * 32 + i * 4);
#pragma unroll
        for (int tt2 = 0; tt2 < 4; tt2++) {
            const int j = kb * 4 + tt2;
            __half h[8];
#pragma unroll
            for (int u = 0; u < 8; u++) {
                int k = 2 * tt2 + (u & 1) + ((u >> 1) & 1) * 8 + ((u >> 2) & 1) * 16;
                h[u] = __float2half_rn(in[k]);
            }
            *reinterpret_cast<uint4*>(img + ((((uint32_t)j) << 4) ^ rx)) =
                *reinterpret_cast<uint4*>(h);
        }
    }
}

// ---------------------------------------------------------------------------
// Prep W + bias: w-images (sample + transpose via 17.4KB smem half-tiles),
// bias chunks appended. Same as round 14 except fast softplus.
// ---------------------------------------------------------------------------
__global__ __launch_bounds__(128)
void prep_wb_kernel(const float* __restrict__ mu,
                    const float* __restrict__ rho,
                    const float* __restrict__ eps,
                    const float* __restrict__ bmu,
                    const float* __restrict__ brho,
                    const float* __restrict__ beps) {
    __shared__ __align__(16) float tl[32][132];   // 16.9KB
    const int gb = blockIdx.x;
    const int t = threadIdx.x;

    if (gb < PW_ITEMS) {
        const int kt = gb & 31, ot = (gb >> 5) & 15, m = gb >> 9;
        char* img = (char*)g_Ws + ((size_t)((m * NOT16 + ot) * NKT + kt)) * IMG_BYTES;
#pragma unroll
        for (int kb = 0; kb < 2; kb++) {
            const size_t base = (size_t)m * I_DIM * O_DIM +
                                (size_t)(kt * 64 + kb * 32) * O_DIM + ot * 128;
#pragma unroll
            for (int i = 0; i < 8; i++) {           // 32 rows x 32 float4
                int c = t + i * 128;
                int r = c >> 5, qq = c & 31;
                size_t idx = base + (size_t)r * O_DIM + qq * 4;
                float4 vm = *reinterpret_cast<const float4*>(mu + idx);
                float4 vr = *reinterpret_cast<const float4*>(rho + idx);
                float4 ve = *reinterpret_cast<const float4*>(eps + idx);
                float4 w;
                w.x = fmaf(softplus_f(vr.x), ve.x, vm.x);
                w.y = fmaf(softplus_f(vr.y), ve.y, vm.y);
                w.z = fmaf(softplus_f(vr.z), ve.z, vm.z);
                w.w = fmaf(softplus_f(vr.w), ve.w, vm.w);
                *reinterpret_cast<float4*>(&tl[r][qq * 4]) = w;
            }
            __syncthreads();
#pragma unroll
            for (int i = 0; i < 4; i++) {           // 128 o x 4 tt
                int c = t + i * 128;
                int o = c >> 2, tt2 = c & 3;
                int j = kb * 4 + tt2;
                __half h[8];
#pragma unroll
                for (int u = 0; u < 8; u++) {
                    int kl = 2 * tt2 + (u & 1) + ((u >> 1) & 1) * 8 + ((u >> 2) & 1) * 16;
                    h[u] = __float2half_rn(tl[kl][o]);
                }
                uint32_t off = (uint32_t)o * 128 +
                               ((((uint32_t)j) << 4) ^ (rev3((uint32_t)o & 7) << 4));
                *reinterpret_cast<uint4*>(img + off) = *reinterpret_cast<uint4*>(h);
            }
            __syncthreads();
        }
    } else {
        // ---- bias ----
        int i = (gb - PW_ITEMS) * 128 + t;
        g_bias[i] = fmaf(softplus_f(brho[i]), beps[i], bmu[i]);
    }
}

// ---------------------------------------------------------------------------
// GEMM (round 14, proven 633.9us / 202 regs): 128 thr, 2 CTAs/SM, full/empty
// mbarriers, no per-tile __syncthreads; producer refills before its full-wait.
// BYTE-IDENTICAL to round 14 — do not touch.
// ---------------------------------------------------------------------------
__global__ __launch_bounds__(128, 2)
void gemm_kernel(float* __restrict__ Out) {
    extern __shared__ __align__(128) uint8_t smem_raw[];
    const uint32_t sb = smem_u32_of(smem_raw);
    const int tid = threadIdx.x, lane = tid & 31, wid = tid >> 5;
    const int gid = lane >> 2, tig = lane & 3;
    const int wm = wid >> 1, wn = wid & 1;
    const int ot = blockIdx.x, bt = blockIdx.y, m = blockIdx.z;

    const char* gA = (const char*)g_Xs + (size_t)((m * NBT + bt) * NKT) * IMG_BYTES;
    const char* gB = (const char*)g_Ws + (size_t)((m * NOT16 + ot) * NKT) * IMG_BYTES;

    if (tid == 0) {
#pragma unroll
        for (int s = 0; s < STAGES; s++) {
            mbar_init(sb + 8 * s, 1);
            mbar_init(sb + 24 + 8 * s, 4);
        }
        asm volatile("fence.proxy.async.shared::cta;" ::: "memory");
    }
    __syncthreads();

    if (tid == 0) {
#pragma unroll
        for (int kt = 0; kt < 2; kt++) {
            uint32_t fb = sb + 8 * kt;
            uint32_t st = sb + SMEM_CTRL + kt * STAGE_BYTES;
            mbar_expect_tx(fb, STAGE_BYTES);
            bulk_g2s(st, gA + (size_t)kt * IMG_BYTES, IMG_BYTES, fb);
            bulk_g2s(st + IMG_BYTES, gB + (size_t)kt * IMG_BYTES, IMG_BYTES, fb);
        }
    }

    float acc[4][8][4];
#pragma unroll
    for (int f = 0; f < 4; f++)
#pragma unroll
        for (int n = 0; n < 8; n++)
#pragma unroll
            for (int q = 0; q < 4; q++) acc[f][n][q] = 0.0f;

    const uint32_t arev = rev3(gid) << 4;
    uint32_t aRow[4], bRow[8];
#pragma unroll
    for (int f = 0; f < 4; f++) aRow[f] = (uint32_t)(wm * 64 + f * 16 + gid) * 128;
#pragma unroll
    for (int n = 0; n < 8; n++) bRow[n] = (uint32_t)(wn * 64 + n * 8 + gid) * 128;

    constexpr int NROUND = (NKT + 2) / 3;  // 11
    for (int rr = 0; rr < NROUND; rr++) {
        const int phf = rr & 1;
#pragma unroll
        for (int ss = 0; ss < 3; ss++) {
            const int kt = rr * 3 + ss;
            if (kt >= NKT) break;

            if (tid == 0 && kt + 2 < NKT) {
                const int s2 = (ss + 2 >= 3) ? ss - 1 : ss + 2;  // compile-time
                if (kt >= 1) {
                    const int phe = (ss == 0) ? ((rr - 1) & 1) : (rr & 1);
                    mbar_wait(sb + 24 + 8 * s2, phe);
                }
                uint32_t fb = sb + 8 * s2;
                uint32_t st = sb + SMEM_CTRL + s2 * STAGE_BYTES;
                mbar_expect_tx(fb, STAGE_BYTES);
                bulk_g2s(st, gA + (size_t)(kt + 2) * IMG_BYTES, IMG_BYTES, fb);
                bulk_g2s(st + IMG_BYTES, gB + (size_t)(kt + 2) * IMG_BYTES, IMG_BYTES, fb);
            }

            mbar_wait(sb + 8 * ss, phf);

            const uint8_t* As = smem_raw + (SMEM_CTRL + ss * STAGE_BYTES);
            const uint8_t* Bs = As + IMG_BYTES;

#pragma unroll
            for (int kb = 0; kb < 2; kb++) {
                const uint32_t gran = (((uint32_t)(kb * 4 + tig)) << 4) ^ arev;
                uint4 aLo[4], aHi[4], bV[8];
#pragma unroll
                for (int f = 0; f < 4; f++) {
                    aLo[f] = *reinterpret_cast<const uint4*>(As + aRow[f] + gran);
                    aHi[f] = *reinterpret_cast<const uint4*>(As + aRow[f] + 8 * 128 + gran);
                }
#pragma unroll
                for (int n = 0; n < 8; n++)
                    bV[n] = *reinterpret_cast<const uint4*>(Bs + bRow[n] + gran);
#pragma unroll
                for (int kg = 0; kg < 2; kg++) {
#pragma unroll
                    for (int f = 0; f < 4; f++) {
                        uint32_t a0 = kg ? aLo[f].z : aLo[f].x;
                        uint32_t a2 = kg ? aLo[f].w : aLo[f].y;
                        uint32_t a1 = kg ? aHi[f].z : aHi[f].x;
                        uint32_t a3 = kg ? aHi[f].w : aHi[f].y;
#pragma unroll
                        for (int n = 0; n < 8; n++) {
                            uint32_t b0 = kg ? bV[n].z : bV[n].x;
                            uint32_t b1 = kg ? bV[n].w : bV[n].y;
                            mma_f16(acc[f][n], a0, a1, a2, a3, b0, b1);
                        }
                    }
                }
            }
            if (lane == 0) mbar_arrive(sb + 24 + 8 * ss);
        }
    }

    // ---- epilogue: add bias, write out ----
    const float* bias = g_bias + m * O_DIM + ot * CT_N;
    const size_t rowbase = (size_t)m * B_DIM + (size_t)bt * CT_M;
#pragma unroll
    for (int f = 0; f < 4; f++) {
        int r0 = wm * 64 + f * 16 + gid;
#pragma unroll
        for (int n = 0; n < 8; n++) {
            int col = wn * 64 + n * 8 + tig * 2;
            float2 bb = *reinterpret_cast<const float2*>(&bias[col]);
            float2 v0, v1;
            v0.x = acc[f][n][0] + bb.x;
            v0.y = acc[f][n][1] + bb.y;
            v1.x = acc[f][n][2] + bb.x;
            v1.y = acc[f][n][3] + bb.y;
            *reinterpret_cast<float2*>(
                &Out[(rowbase + r0) * O_DIM + (size_t)ot * CT_N + col]) = v0;
            *reinterpret_cast<float2*>(
                &Out[(rowbase + r0 + 8) * O_DIM + (size_t)ot * CT_N + col]) = v1;
        }
    }
}

// ---------------------------------------------------------------------------
// Launch (single stream, graph-safe).
// Inputs: x, weight_mu, weight_rho, bias_mu, bias_rho, eps_w, eps_b
// ---------------------------------------------------------------------------
extern "C" void kernel_launch(void* const* d_in, const int* in_sizes, int n_in,
                              void* d_out, int out_size) {
    const float* x     = (const float*)d_in[0];
    const float* w_mu  = (const float*)d_in[1];
    const float* w_rho = (const float*)d_in[2];
    const float* b_mu  = (const float*)d_in[3];
    const float* b_rho = (const float*)d_in[4];
    const float* eps_w = (const float*)d_in[5];
    const float* eps_b = (const float*)d_in[6];
    float* out = (float*)d_out;

    cudaFuncSetAttribute(gemm_kernel, cudaFuncAttributeMaxDynamicSharedMemorySize,
                         SMEM_BYTES);

    prep_x_kernel<<<PX_ITEMS, 128>>>(x);                               // 8192 blocks
    prep_wb_kernel<<<PW_ITEMS + PB_ITEMS, 128>>>(w_mu, w_rho, eps_w,
                                                 b_mu, b_rho, eps_b);  // 4224 blocks
    gemm_kernel<<<dim3(NOT16, NBT, M_ENS), 128, SMEM_BYTES>>>(out);
}

// round 17
// speedup vs baseline: 1.0574x; 1.0285x over previous
#include <cuda_runtime.h>
#include <cuda_fp16.h>
#include <cstdint>

// ---------------------------------------------------------------------------
// Problem shape
// ---------------------------------------------------------------------------
constexpr int M_ENS = 8, B_DIM = 4096, I_DIM = 2048, O_DIM = 2048;

// GEMM tiling: CTA = 128x128, K-tile 64, 4 warps (2x2), 2 CTAs/SM.
constexpr int CT_M = 128, CT_N = 128, CT_K = 64;
constexpr int NKT = I_DIM / CT_K;    // 32
constexpr int NBT = B_DIM / CT_M;    // 32
constexpr int NOT16 = O_DIM / CT_N;  // 16
constexpr int IMG_BYTES = CT_M * CT_K * 2;      // 16384
constexpr int STAGE_BYTES = 2 * IMG_BYTES;      // 32768
constexpr int STAGES = 3;
constexpr int SMEM_CTRL = 128;
constexpr int SMEM_BYTES = SMEM_CTRL + STAGES * STAGE_BYTES;  // 98432

// prep enumeration
constexpr int PX_ITEMS = M_ENS * NBT * NKT;      // 8192 x-images
constexpr int PW_ITEMS = M_ENS * NOT16 * NKT;    // 4096 w-images
constexpr int PB_ITEMS = (M_ENS * O_DIM) / 128;  // 128 bias chunks

// ---------------------------------------------------------------------------
// Scratch (device globals; no cudaMalloc allowed).
// Images: pre-swizzled smem images (layout per round-7 comment).
// ---------------------------------------------------------------------------
__device__ __align__(128) __half g_Xs[(size_t)M_ENS * B_DIM * I_DIM];
__device__ __align__(128) __half g_Ws[(size_t)M_ENS * O_DIM * I_DIM];
__device__ float g_bias[M_ENS * O_DIM];

// ---------------------------------------------------------------------------
// Helpers
// ---------------------------------------------------------------------------
__device__ __forceinline__ float softplus_f(float r) {
    // fast softplus: __logf abs err ~4e-7 near 1 -> negligible vs fp16 quant
    return (r > 15.0f) ? r : __logf(1.0f + __expf(r));
}
__device__ __forceinline__ uint32_t smem_u32_of(const void* p) {
    uint32_t a;
    asm("{ .reg .u64 t; cvta.to.shared.u64 t, %1; cvt.u32.u64 %0, t; }"
        : "=r"(a) : "l"(p));
    return a;
}
__device__ __forceinline__ uint32_t rev3(uint32_t x) {
    return ((x & 1u) << 2) | (x & 2u) | ((x >> 2) & 1u);
}
__device__ __forceinline__ void mbar_init(uint32_t mbar, uint32_t cnt) {
    asm volatile("mbarrier.init.shared.b64 [%0], %1;" :: "r"(mbar), "r"(cnt) : "memory");
}
__device__ __forceinline__ void mbar_expect_tx(uint32_t mbar, uint32_t bytes) {
    asm volatile("mbarrier.arrive.expect_tx.shared.b64 _, [%0], %1;"
                 :: "r"(mbar), "r"(bytes) : "memory");
}
__device__ __forceinline__ void mbar_arrive(uint32_t mbar) {
    asm volatile("mbarrier.arrive.shared.b64 _, [%0];" :: "r"(mbar) : "memory");
}
__device__ __forceinline__ void mbar_wait(uint32_t mbar, uint32_t parity) {
    asm volatile(
        "{\n\t.reg .pred P;\n\t"
        "W_%=:\n\t"
        "mbarrier.try_wait.parity.acquire.cta.shared::cta.b64 P, [%0], %1, 0x989680;\n\t"
        "@P bra.uni D_%=;\n\t"
        "bra.uni W_%=;\n\t"
        "D_%=:\n\t}"
        :: "r"(mbar), "r"(parity) : "memory");
}
__device__ __forceinline__ void bulk_g2s(uint32_t dst, const void* src,
                                         uint32_t bytes, uint32_t mbar) {
    asm volatile(
        "cp.async.bulk.shared::cluster.global.mbarrier::complete_tx::bytes "
        "[%0], [%1], %2, [%3];"
        :: "r"(dst), "l"(src), "r"(bytes), "r"(mbar) : "memory");
}
__device__ __forceinline__ void mma_f16(float* c, uint32_t a0, uint32_t a1,
                                        uint32_t a2, uint32_t a3,
                                        uint32_t b0, uint32_t b1) {
    asm volatile(
        "mma.sync.aligned.m16n8k16.row.col.f32.f16.f16.f32 "
        "{%0,%1,%2,%3}, {%4,%5,%6,%7}, {%8,%9}, {%0,%1,%2,%3};"
        : "+f"(c[0]), "+f"(c[1]), "+f"(c[2]), "+f"(c[3])
        : "r"(a0), "r"(a1), "r"(a2), "r"(a3), "r"(b0), "r"(b1));
}

// ---------------------------------------------------------------------------
// Prep X (round-14 form, standalone): one image per 128-thread block, 17.4KB
// smem half-tiles. Phase-2 mapping keeps stores COALESCED: 8 consecutive
// lanes write the 8 granules of one row (warp = 4x128B contiguous).
// ---------------------------------------------------------------------------
__global__ __launch_bounds__(128)
void prep_x_kernel(const float* __restrict__ x) {
    __shared__ __align__(16) float tl[64][68];   // 17408 B
    const int gb = blockIdx.x;
    const int t = threadIdx.x;
    const int kt = gb & 31, bt = (gb >> 5) & 31, m = gb >> 10;
    char* img = (char*)g_Xs + ((size_t)((m * NBT + bt) * NKT + kt)) * IMG_BYTES;

#pragma unroll
    for (int half = 0; half < 2; half++) {
        const float* src =
            x + ((size_t)(m * B_DIM + bt * 128 + half * 64)) * I_DIM + kt * 64;
#pragma unroll
        for (int i = 0; i < 8; i++) {           // 64 rows x 16 float4
            int c = t + i * 128;
            int r = c >> 4, q = c & 15;
            float4 v = *reinterpret_cast<const float4*>(src + (size_t)r * I_DIM + q * 4);
            *reinterpret_cast<float4*>(&tl[r][q * 4]) = v;
        }
        __syncthreads();
#pragma unroll
        for (int i = 0; i < 4; i++) {           // 512 granule slots
            int c = t + i * 128;
            int r = c >> 3, j = c & 7;
            int kb = j >> 2, tt2 = j & 3;
            __half h[8];
#pragma unroll
            for (int u = 0; u < 8; u++) {
                int k = kb * 32 + 2 * tt2 + (u & 1) + ((u >> 1) & 1) * 8 +
                        ((u >> 2) & 1) * 16;
                h[u] = __float2half_rn(tl[r][k]);
            }
            uint32_t off = (uint32_t)(half * 64 + r) * 128 +
                           ((((uint32_t)j) << 4) ^ (rev3((uint32_t)r & 7) << 4));
            *reinterpret_cast<uint4*>(img + off) = *reinterpret_cast<uint4*>(h);
        }
        __syncthreads();
    }
}

// ---------------------------------------------------------------------------
// Prep W + bias (round-16 form): sample + transpose via 16.9KB smem
// half-tiles, fast softplus; bias chunks appended.
// ---------------------------------------------------------------------------
__global__ __launch_bounds__(128)
void prep_wb_kernel(const float* __restrict__ mu,
                    const float* __restrict__ rho,
                    const float* __restrict__ eps,
                    const float* __restrict__ bmu,
                    const float* __restrict__ brho,
                    const float* __restrict__ beps) {
    __shared__ __align__(16) float tl[32][132];   // 16.9KB
    const int gb = blockIdx.x;
    const int t = threadIdx.x;

    if (gb < PW_ITEMS) {
        const int kt = gb & 31, ot = (gb >> 5) & 15, m = gb >> 9;
        char* img = (char*)g_Ws + ((size_t)((m * NOT16 + ot) * NKT + kt)) * IMG_BYTES;
#pragma unroll
        for (int kb = 0; kb < 2; kb++) {
            const size_t base = (size_t)m * I_DIM * O_DIM +
                                (size_t)(kt * 64 + kb * 32) * O_DIM + ot * 128;
#pragma unroll
            for (int i = 0; i < 8; i++) {           // 32 rows x 32 float4
                int c = t + i * 128;
                int r = c >> 5, qq = c & 31;
                size_t idx = base + (size_t)r * O_DIM + qq * 4;
                float4 vm = *reinterpret_cast<const float4*>(mu + idx);
                float4 vr = *reinterpret_cast<const float4*>(rho + idx);
                float4 ve = *reinterpret_cast<const float4*>(eps + idx);
                float4 w;
                w.x = fmaf(softplus_f(vr.x), ve.x, vm.x);
                w.y = fmaf(softplus_f(vr.y), ve.y, vm.y);
                w.z = fmaf(softplus_f(vr.z), ve.z, vm.z);
                w.w = fmaf(softplus_f(vr.w), ve.w, vm.w);
                *reinterpret_cast<float4*>(&tl[r][qq * 4]) = w;
            }
            __syncthreads();
#pragma unroll
            for (int i = 0; i < 4; i++) {           // 128 o x 4 tt
                int c = t + i * 128;
                int o = c >> 2, tt2 = c & 3;
                int j = kb * 4 + tt2;
                __half h[8];
#pragma unroll
                for (int u = 0; u < 8; u++) {
                    int kl = 2 * tt2 + (u & 1) + ((u >> 1) & 1) * 8 + ((u >> 2) & 1) * 16;
                    h[u] = __float2half_rn(tl[kl][o]);
                }
                uint32_t off = (uint32_t)o * 128 +
                               ((((uint32_t)j) << 4) ^ (rev3((uint32_t)o & 7) << 4));
                *reinterpret_cast<uint4*>(img + off) = *reinterpret_cast<uint4*>(h);
            }
            __syncthreads();
        }
    } else {
        // ---- bias ----
        int i = (gb - PW_ITEMS) * 128 + t;
        g_bias[i] = fmaf(softplus_f(brho[i]), beps[i], bmu[i]);
    }
}

// ---------------------------------------------------------------------------
// GEMM (round 14, proven 633.9us / 202 regs): 128 thr, 2 CTAs/SM, full/empty
// mbarriers, no per-tile __syncthreads; producer refills before its full-wait.
// BYTE-IDENTICAL to round 14 — do not touch.
// ---------------------------------------------------------------------------
__global__ __launch_bounds__(128, 2)
void gemm_kernel(float* __restrict__ Out) {
    extern __shared__ __align__(128) uint8_t smem_raw[];
    const uint32_t sb = smem_u32_of(smem_raw);
    const int tid = threadIdx.x, lane = tid & 31, wid = tid >> 5;
    const int gid = lane >> 2, tig = lane & 3;
    const int wm = wid >> 1, wn = wid & 1;
    const int ot = blockIdx.x, bt = blockIdx.y, m = blockIdx.z;

    const char* gA = (const char*)g_Xs + (size_t)((m * NBT + bt) * NKT) * IMG_BYTES;
    const char* gB = (const char*)g_Ws + (size_t)((m * NOT16 + ot) * NKT) * IMG_BYTES;

    if (tid == 0) {
#pragma unroll
        for (int s = 0; s < STAGES; s++) {
            mbar_init(sb + 8 * s, 1);
            mbar_init(sb + 24 + 8 * s, 4);
        }
        asm volatile("fence.proxy.async.shared::cta;" ::: "memory");
    }
    __syncthreads();

    if (tid == 0) {
#pragma unroll
        for (int kt = 0; kt < 2; kt++) {
            uint32_t fb = sb + 8 * kt;
            uint32_t st = sb + SMEM_CTRL + kt * STAGE_BYTES;
            mbar_expect_tx(fb, STAGE_BYTES);
            bulk_g2s(st, gA + (size_t)kt * IMG_BYTES, IMG_BYTES, fb);
            bulk_g2s(st + IMG_BYTES, gB + (size_t)kt * IMG_BYTES, IMG_BYTES, fb);
        }
    }

    float acc[4][8][4];
#pragma unroll
    for (int f = 0; f < 4; f++)
#pragma unroll
        for (int n = 0; n < 8; n++)
#pragma unroll
            for (int q = 0; q < 4; q++) acc[f][n][q] = 0.0f;

    const uint32_t arev = rev3(gid) << 4;
    uint32_t aRow[4], bRow[8];
#pragma unroll
    for (int f = 0; f < 4; f++) aRow[f] = (uint32_t)(wm * 64 + f * 16 + gid) * 128;
#pragma unroll
    for (int n = 0; n < 8; n++) bRow[n] = (uint32_t)(wn * 64 + n * 8 + gid) * 128;

    constexpr int NROUND = (NKT + 2) / 3;  // 11
    for (int rr = 0; rr < NROUND; rr++) {
        const int phf = rr & 1;
#pragma unroll
        for (int ss = 0; ss < 3; ss++) {
            const int kt = rr * 3 + ss;
            if (kt >= NKT) break;

            if (tid == 0 && kt + 2 < NKT) {
                const int s2 = (ss + 2 >= 3) ? ss - 1 : ss + 2;  // compile-time
                if (kt >= 1) {
                    const int phe = (ss == 0) ? ((rr - 1) & 1) : (rr & 1);
                    mbar_wait(sb + 24 + 8 * s2, phe);
                }
                uint32_t fb = sb + 8 * s2;
                uint32_t st = sb + SMEM_CTRL + s2 * STAGE_BYTES;
                mbar_expect_tx(fb, STAGE_BYTES);
                bulk_g2s(st, gA + (size_t)(kt + 2) * IMG_BYTES, IMG_BYTES, fb);
                bulk_g2s(st + IMG_BYTES, gB + (size_t)(kt + 2) * IMG_BYTES, IMG_BYTES, fb);
            }

            mbar_wait(sb + 8 * ss, phf);

            const uint8_t* As = smem_raw + (SMEM_CTRL + ss * STAGE_BYTES);
            const uint8_t* Bs = As + IMG_BYTES;

#pragma unroll
            for (int kb = 0; kb < 2; kb++) {
                const uint32_t gran = (((uint32_t)(kb * 4 + tig)) << 4) ^ arev;
                uint4 aLo[4], aHi[4], bV[8];
#pragma unroll
                for (int f = 0; f < 4; f++) {
                    aLo[f] = *reinterpret_cast<const uint4*>(As + aRow[f] + gran);
                    aHi[f] = *reinterpret_cast<const uint4*>(As + aRow[f] + 8 * 128 + gran);
                }
#pragma unroll
                for (int n = 0; n < 8; n++)
                    bV[n] = *reinterpret_cast<const uint4*>(Bs + bRow[n] + gran);
#pragma unroll
                for (int kg = 0; kg < 2; kg++) {
#pragma unroll
                    for (int f = 0; f < 4; f++) {
                        uint32_t a0 = kg ? aLo[f].z : aLo[f].x;
                        uint32_t a2 = kg ? aLo[f].w : aLo[f].y;
                        uint32_t a1 = kg ? aHi[f].z : aHi[f].x;
                        uint32_t a3 = kg ? aHi[f].w : aHi[f].y;
#pragma unroll
                        for (int n = 0; n < 8; n++) {
                            uint32_t b0 = kg ? bV[n].z : bV[n].x;
                            uint32_t b1 = kg ? bV[n].w : bV[n].y;
                            mma_f16(acc[f][n], a0, a1, a2, a3, b0, b1);
                        }
                    }
                }
            }
            if (lane == 0) mbar_arrive(sb + 24 + 8 * ss);
        }
    }

    // ---- epilogue: add bias, write out ----
    const float* bias = g_bias + m * O_DIM + ot * CT_N;
    const size_t rowbase = (size_t)m * B_DIM + (size_t)bt * CT_M;
#pragma unroll
    for (int f = 0; f < 4; f++) {
        int r0 = wm * 64 + f * 16 + gid;
#pragma unroll
        for (int n = 0; n < 8; n++) {
            int col = wn * 64 + n * 8 + tig * 2;
            float2 bb = *reinterpret_cast<const float2*>(&bias[col]);
            float2 v0, v1;
            v0.x = acc[f][n][0] + bb.x;
            v0.y = acc[f][n][1] + bb.y;
            v1.x = acc[f][n][2] + bb.x;
            v1.y = acc[f][n][3] + bb.y;
            *reinterpret_cast<float2*>(
                &Out[(rowbase + r0) * O_DIM + (size_t)ot * CT_N + col]) = v0;
            *reinterpret_cast<float2*>(
                &Out[(rowbase + r0 + 8) * O_DIM + (size_t)ot * CT_N + col]) = v1;
        }
    }
}

// ---------------------------------------------------------------------------
// Launch (single stream, graph-safe).
// Inputs: x, weight_mu, weight_rho, bias_mu, bias_rho, eps_w, eps_b
// ---------------------------------------------------------------------------
extern "C" void kernel_launch(void* const* d_in, const int* in_sizes, int n_in,
                              void* d_out, int out_size) {
    const float* x     = (const float*)d_in[0];
    const float* w_mu  = (const float*)d_in[1];
    const float* w_rho = (const float*)d_in[2];
    const float* b_mu  = (const float*)d_in[3];
    const float* b_rho = (const float*)d_in[4];
    const float* eps_w = (const float*)d_in[5];
    const float* eps_b = (const float*)d_in[6];
    float* out = (float*)d_out;

    cudaFuncSetAttribute(gemm_kernel, cudaFuncAttributeMaxDynamicSharedMemorySize,
                         SMEM_BYTES);

    prep_x_kernel<<<PX_ITEMS, 128>>>(x);                               // 8192 blocks
    prep_wb_kernel<<<PW_ITEMS + PB_ITEMS, 128>>>(w_mu, w_rho, eps_w,
                                                 b_mu, b_rho, eps_b);  // 4224 blocks
    gemm_kernel<<<dim3(NOT16, NBT, M_ENS), 128, SMEM_BYTES>>>(out);
}